// round 2
// baseline (speedup 1.0000x reference)
#include <cuda_runtime.h>
#include <stdint.h>

// ROISelect: per-row top-k(score) + ROI gather, two-phase.
//   Phase A: 1024 CTAs stream-scan score (MLP=8 batched float4 loads),
//            filter >= 2.5 into global candidate scratch (1 global atomic/CTA).
//   Phase B: 128 CTAs sort each row's ~1.1K candidates (bitonic, u64 keys
//            packing value|~index for tf.nn.top_k tie order), emit sorted
//            top-256 scores + gathered ROI rows. Exact radix-select fallback
//            if the statistical threshold ever misfires.

#define B_ROWS 128
#define N_COLS 131072
#define K_TOP  256
#define CAP    4096

#define SLICES      8
#define A_TPB       512
#define SLICE_ELEMS (N_COLS / SLICES)      // 16384
#define SLICE_V4    (SLICE_ELEMS / 4)      // 4096
#define A_ITERS     (SLICE_V4 / A_TPB)     // 8
#define SCAP        2048                   // per-CTA stage capacity

#define B_TPB     1024
#define VEC_ITERS (N_COLS / 4 / B_TPB)     // 32 (fallback only)

__device__ unsigned long long g_cand[B_ROWS * CAP];
__device__ unsigned int       g_cnt[B_ROWS];

__device__ __forceinline__ unsigned int f2u(float f) {
    unsigned int b = __float_as_uint(f);
    return (b & 0x80000000u) ? ~b : (b | 0x80000000u);
}
__device__ __forceinline__ float u2f(unsigned int u) {
    unsigned int b = (u & 0x80000000u) ? (u ^ 0x80000000u) : ~u;
    return __uint_as_float(b);
}

// ---------------- Phase A: streaming filter ----------------
__global__ __launch_bounds__(A_TPB, 2)
void roisel_scan_kernel(const float* __restrict__ score)
{
    __shared__ unsigned long long stage[SCAP];
    __shared__ int s_cnt;
    __shared__ unsigned int s_base;

    const int tid   = threadIdx.x;
    const int slice = blockIdx.x;
    const int row   = blockIdx.y;

    if (tid == 0) s_cnt = 0;
    __syncthreads();

    const float4* sc4 =
        (const float4*)(score + (size_t)row * N_COLS + (size_t)slice * SLICE_ELEMS);

    // Front-batched loads: 8 independent LDG.128 per thread.
    float4 v[A_ITERS];
    #pragma unroll
    for (int j = 0; j < A_ITERS; ++j)
        v[j] = sc4[tid + j * A_TPB];

    const float TGUESS = 2.5f;
    const int gbase = slice * SLICE_ELEMS;
    #pragma unroll
    for (int j = 0; j < A_ITERS; ++j) {
        int ebase = gbase + (tid + j * A_TPB) * 4;
        float vals[4] = {v[j].x, v[j].y, v[j].z, v[j].w};
        #pragma unroll
        for (int c = 0; c < 4; ++c) {
            if (vals[c] >= TGUESS) {
                unsigned int u = __float_as_uint(vals[c]) | 0x80000000u; // positive fp32
                int pos = atomicAdd(&s_cnt, 1);
                if (pos < SCAP)
                    stage[pos] = ((unsigned long long)u << 32)
                               | (unsigned int)~(unsigned int)(ebase + c);
            }
        }
    }
    __syncthreads();

    int raw = s_cnt;
    int cnt = min(raw, SCAP);
    if (tid == 0) {
        unsigned int add = (unsigned int)raw;
        if (raw > SCAP) add += (1u << 20);   // force fallback in phase B
        s_base = atomicAdd(&g_cnt[row], add);
    }
    __syncthreads();

    unsigned int base = s_base;
    unsigned long long* dst = g_cand + (size_t)row * CAP;
    for (int i = tid; i < cnt; i += A_TPB) {
        unsigned int p = base + i;
        if (p < CAP) dst[p] = stage[i];
    }
}

// ---------------- Phase B: sort + emit ----------------
__global__ __launch_bounds__(B_TPB, 1)
void roisel_sort_kernel(const float* __restrict__ score,
                        const float* __restrict__ roi,
                        float* __restrict__ out_roi,
                        float* __restrict__ out_score)
{
    __shared__ int s_bin;
    __shared__ int s_cnt;
    extern __shared__ unsigned long long cand[];   // CAP entries = 32 KB

    const int tid = threadIdx.x;
    const int row = blockIdx.x;

    unsigned int count = g_cnt[row];
    const unsigned long long* src = g_cand + (size_t)row * CAP;

    if (count >= K_TOP && count <= CAP) {
        // Fast path: pull candidates from scratch.
        for (unsigned int i = tid; i < count; i += B_TPB)
            cand[i] = src[i];
    } else {
        // ---------- Exact fallback: 12-bit radix select over the raw row ----------
        const float4* sc4 = (const float4*)(score + (size_t)row * N_COLS);
        unsigned int* hist  = (unsigned int*)cand;   // 4096 bins (aliased)
        unsigned int* sdata = hist + 4096;           // 1024 thread sums
        for (int i = tid; i < 4096; i += B_TPB) hist[i] = 0;
        if (tid == 0) s_cnt = 0;
        __syncthreads();

        for (int i = 0; i < VEC_ITERS; ++i) {
            float4 f = sc4[tid + i * B_TPB];
            float vals[4] = {f.x, f.y, f.z, f.w};
            #pragma unroll
            for (int c = 0; c < 4; ++c)
                atomicAdd(&hist[f2u(vals[c]) >> 20], 1u);
        }
        __syncthreads();

        unsigned int h0 = hist[4*tid+0], h1 = hist[4*tid+1];
        unsigned int h2 = hist[4*tid+2], h3 = hist[4*tid+3];
        sdata[tid] = h0 + h1 + h2 + h3;
        __syncthreads();
        for (int d = 1; d < B_TPB; d <<= 1) {       // inclusive suffix scan
            unsigned int vv = (tid + d < B_TPB) ? sdata[tid + d] : 0u;
            __syncthreads();
            sdata[tid] += vv;
            __syncthreads();
        }
        unsigned int Anext = (tid + 1 < B_TPB) ? sdata[tid + 1] : 0u;
        unsigned int cum3 = Anext + h3;
        unsigned int cum2 = cum3 + h2;
        unsigned int cum1 = cum2 + h1;
        unsigned int cum0 = cum1 + h0;
        if (cum3 >= K_TOP && Anext < K_TOP) s_bin = 4*tid + 3;
        if (cum2 >= K_TOP && cum3  < K_TOP) s_bin = 4*tid + 2;
        if (cum1 >= K_TOP && cum2  < K_TOP) s_bin = 4*tid + 1;
        if (cum0 >= K_TOP && cum1  < K_TOP) s_bin = 4*tid + 0;
        __syncthreads();
        unsigned int uthr = (unsigned int)s_bin << 20;
        __syncthreads();   // uthr read by all; hist region can be overwritten

        for (int i = 0; i < VEC_ITERS; ++i) {
            int v4 = tid + i * B_TPB;
            float4 f = sc4[v4];
            int ebase = v4 * 4;
            float vals[4] = {f.x, f.y, f.z, f.w};
            #pragma unroll
            for (int c = 0; c < 4; ++c) {
                unsigned int u = f2u(vals[c]);
                if (u >= uthr) {
                    int pos = atomicAdd(&s_cnt, 1);
                    if (pos < CAP)
                        cand[pos] = ((unsigned long long)u << 32)
                                  | (unsigned int)~(unsigned int)(ebase + c);
                }
            }
        }
        __syncthreads();
        count = min(s_cnt, CAP);
    }

    // Reset counter for the next launch (deterministic across graph replays;
    // counters are also memset before phase A, this is belt-and-braces).
    if (tid == 0) g_cnt[row] = 0;

    // ---------- Pad to power of two ----------
    int n = K_TOP;
    while (n < (int)count) n <<= 1;
    for (int i = (int)count + tid; i < n; i += B_TPB) cand[i] = 0ULL;
    __syncthreads();

    // ---------- Bitonic sort, descending ----------
    for (int size = 2; size <= n; size <<= 1) {
        for (int stride = size >> 1; stride > 0; stride >>= 1) {
            for (int i = tid; i < n; i += B_TPB) {
                int j = i ^ stride;
                if (j > i) {
                    unsigned long long a = cand[i];
                    unsigned long long b = cand[j];
                    bool desc = ((i & size) == 0);
                    if (desc ? (a < b) : (a > b)) { cand[i] = b; cand[j] = a; }
                }
            }
            __syncthreads();
        }
    }

    // ---------- Emit top-256: sorted scores + ROI gather ----------
    if (tid < K_TOP) {
        unsigned long long p = cand[tid];
        unsigned int u   = (unsigned int)(p >> 32);
        unsigned int idx = ~(unsigned int)p;
        out_score[row * K_TOP + tid] = u2f(u);
        const float4* r4 = (const float4*)roi;
        float4 rv = r4[(size_t)row * N_COLS + idx];
        ((float4*)out_roi)[row * K_TOP + tid] = rv;
    }
}

extern "C" void kernel_launch(void* const* d_in, const int* in_sizes, int n_in,
                              void* d_out, int out_size) {
    (void)in_sizes; (void)n_in; (void)out_size;
    const float* score = (const float*)d_in[0];
    const float* roi   = (const float*)d_in[1];
    float* out_roi   = (float*)d_out;                               // [128,256,4]
    float* out_score = (float*)d_out + (size_t)B_ROWS * K_TOP * 4;  // [128,256]

    void* cnt_ptr = nullptr;
    cudaGetSymbolAddress(&cnt_ptr, g_cnt);
    cudaMemsetAsync(cnt_ptr, 0, sizeof(unsigned int) * B_ROWS);

    dim3 gridA(SLICES, B_ROWS);
    roisel_scan_kernel<<<gridA, A_TPB>>>(score);
    roisel_sort_kernel<<<B_ROWS, B_TPB, CAP * sizeof(unsigned long long)>>>(
        score, roi, out_roi, out_score);
}